// round 4
// baseline (speedup 1.0000x reference)
#include <cuda_runtime.h>

#define CH 32
#define SEGS 33
#define NMAX 50000
#define EMAX 200000
#define FULL 0xffffffffu

// ---- device-global scratch ----
__device__ float g_bp_e[32], g_bp_a[32];          // compacted breakpoints, sentinel 2.0
__device__ float g_trep_e[SEGS], g_trep_a[SEGS];  // per-segment representative t
__device__ int   g_nseg_e, g_nseg_a;              // effective segment counts
__device__ unsigned long long g_AB[SEGS * 1024];  // (s,i,lane) packed {A,B} float2
__device__ float g_aA[SEGS * 32], g_aB[SEGS * 32];
__device__ int   g_ecnt[SEGS];                    // per-segment edge count / cursor
__device__ int   g_ebuck[SEGS * EMAX];            // bucketed edge ids
__device__ __align__(16) float g_cnt[SEGS * NMAX];
__device__ __align__(16) float g_ts[SEGS * NMAX];
__device__ __align__(16) float g_xdup[NMAX * 64]; // x duplicated: {x0,x0,x1,x1,...}

// ---------------------------------------------------------------------------
// K1: compact breakpoints to (0,1) via parallel rank sort. Warp0=edge, warp1=angle.
// ---------------------------------------------------------------------------
__global__ void k_pre(const float* __restrict__ eW1, const float* __restrict__ eb1,
                      const float* __restrict__ aW1, const float* __restrict__ ab1) {
    __shared__ float sorted[2][33];
    int warp = threadIdx.x >> 5, lane = threadIdx.x & 31;
    if (threadIdx.x < SEGS) g_ecnt[threadIdx.x] = 0;
    if (warp > 1) return;

    const float* W = (warp == 0) ? eW1 : aW1;
    const float* B = (warp == 0) ? eb1 : ab1;
    float w = W[lane], b = B[lane];
    float p = (w != 0.0f) ? (-b / w) : -1.0f;
    bool valid = (p > 0.0f && p < 1.0f);
    unsigned vm = __ballot_sync(FULL, valid);
    int c = __popc(vm);

    int rank = 0;
    #pragma unroll
    for (int i = 0; i < 32; i++) {
        float pi = __shfl_sync(FULL, p, i);
        bool vi = (vm >> i) & 1;
        if (vi && (pi < p || (pi == p && i < lane))) rank++;
    }
    if (valid) sorted[warp][rank] = p;
    __syncwarp();

    float bpv = (lane < c) ? sorted[warp][lane] : 2.0f;
    if (warp == 0) g_bp_e[lane] = bpv; else g_bp_a[lane] = bpv;
    if (lane == 0) { if (warp == 0) g_nseg_e = c + 1; else g_nseg_a = c + 1; }

    for (int s = lane; s <= c; s += 32) {
        float lo = (s == 0) ? 0.0f : sorted[warp][s - 1];
        float hi = (s == c) ? 1.0f : sorted[warp][s];
        float tr = 0.5f * (lo + hi);
        if (warp == 0) g_trep_e[s] = tr; else g_trep_a[s] = tr;
    }
}

// ---------------------------------------------------------------------------
// K2: table build (blocks 0..SEGS) + vectorized zeroing (remaining blocks)
// ---------------------------------------------------------------------------
__global__ void k_setup(const float* __restrict__ eW1, const float* __restrict__ eb1,
                        const float* __restrict__ eW2, const float* __restrict__ eb2,
                        const float* __restrict__ aW1, const float* __restrict__ ab1,
                        const float* __restrict__ aW2, const float* __restrict__ ab2,
                        float* __restrict__ out, int N) {
    int blk = blockIdx.x;
    if (blk < SEGS) {
        int s = blk;
        if (s >= g_nseg_e) return;
        __shared__ float w1[32], b1[32];
        if (threadIdx.x < 32) { w1[threadIdx.x] = eW1[threadIdx.x]; b1[threadIdx.x] = eb1[threadIdx.x]; }
        __syncthreads();
        float trep = g_trep_e[s];
        float* ABf = (float*)g_AB;
        for (int io = threadIdx.x; io < 1024; io += blockDim.x) {
            float a = eb2[io], b = 0.0f;
            #pragma unroll
            for (int k = 0; k < 32; k++) {
                if (w1[k] * trep + b1[k] > 0.0f) {
                    float w2 = eW2[k * 1024 + io];
                    a = fmaf(b1[k], w2, a);
                    b = fmaf(w1[k], w2, b);
                }
            }
            int i = io >> 5, o = io & 31;
            int base = (((s * 32 + i) * 32) + o) * 2;
            ABf[base + 0] = a;
            ABf[base + 1] = b;
        }
    } else if (blk == SEGS) {
        int ns = g_nseg_a;
        for (int idx = threadIdx.x; idx < ns * 32; idx += blockDim.x) {
            int s2 = idx >> 5, o = idx & 31;
            float trep = g_trep_a[s2];
            float a = ab2[o], b = 0.0f;
            #pragma unroll
            for (int k = 0; k < 32; k++) {
                float w = aW1[k], bb = ab1[k];
                if (w * trep + bb > 0.0f) {
                    float w2 = aW2[k * 32 + o];
                    a = fmaf(bb, w2, a);
                    b = fmaf(w, w2, b);
                }
            }
            g_aA[idx] = a;
            g_aB[idx] = b;
        }
    } else {
        // vectorized zeroing: out (N*32 floats) + g_cnt/g_ts (nseg_a*NMAX floats each)
        float4 z = make_float4(0.f, 0.f, 0.f, 0.f);
        long no = (long)N * 8;                       // float4 count for out
        long nc = (long)g_nseg_a * (NMAX / 4);       // float4 count for cnt/ts each
        long nb = (long)gridDim.x - SEGS - 1;
        long gid = (long)(blk - SEGS - 1) * blockDim.x + threadIdx.x;
        long stride = nb * blockDim.x;
        float4* o4 = (float4*)out;
        float4* c4 = (float4*)g_cnt;
        float4* t4 = (float4*)g_ts;
        for (long i = gid; i < no; i += stride) o4[i] = z;
        for (long i = gid; i < nc; i += stride) { c4[i] = z; t4[i] = z; }
    }
}

// ---------------------------------------------------------------------------
// K3: front pass — edge bucketing + angle scatter + x duplication
// ---------------------------------------------------------------------------
__global__ void k_front(const int* __restrict__ ei, const float* __restrict__ ea,
                        const int* __restrict__ ai, const float* __restrict__ ang,
                        const float* __restrict__ x,
                        int E, int A, int N) {
    __shared__ float sbe[32], sba[32];
    if (threadIdx.x < 32) { sbe[threadIdx.x] = g_bp_e[threadIdx.x]; sba[threadIdx.x] = g_bp_a[threadIdx.x]; }
    __syncthreads();
    int i = blockIdx.x * blockDim.x + threadIdx.x;
    int lane = threadIdx.x & 31;

    // ---- x duplication: x (N*32 floats) -> g_xdup (N*64, each value doubled) ----
    int ndup4 = N * 8;   // float4 count of x
    if (i < ndup4) {
        float4 v = ((const float4*)x)[i];
        float4* xd4 = (float4*)g_xdup;
        xd4[2 * i + 0] = make_float4(v.x, v.x, v.y, v.y);
        xd4[2 * i + 1] = make_float4(v.z, v.z, v.w, v.w);
    }

    // ---- edge bucketing (warp-aggregated cursor atomics) ----
    bool valid = (i < E);
    float t = valid ? __ldg(ea + i) : 0.0f;
    int seg = 0;
    #pragma unroll
    for (int k = 0; k < 32; k++) seg += (sbe[k] <= t) ? 1 : 0;
    int ns = g_nseg_e;
    for (int s = 0; s < ns; s++) {
        unsigned mask = __ballot_sync(FULL, valid && (seg == s));
        if (mask) {
            int leader = __ffs(mask) - 1;
            int base = 0;
            if (lane == leader) base = atomicAdd(&g_ecnt[s], __popc(mask));
            base = __shfl_sync(FULL, base, leader);
            if (valid && seg == s) {
                int pos = base + __popc(mask & ((1u << lane) - 1u));
                g_ebuck[s * EMAX + pos] = i;
            }
        }
    }

    // ---- angle scatter ----
    if (i < A) {
        float ta = __ldg(ang + i);
        int j = __ldg(ai + A + i);   // angle_index[1] = center node
        int sa = 0;
        #pragma unroll
        for (int k = 0; k < 32; k++) sa += (sba[k] <= ta) ? 1 : 0;
        atomicAdd(&g_cnt[sa * NMAX + j], 1.0f);
        atomicAdd(&g_ts[sa * NMAX + j], ta);
    }
}

// ---------------------------------------------------------------------------
// K4: edge branch (y slices 0..SEGS-1): warp per 2 edges, register A/B table,
//     uniform LDG.128 of pre-duplicated x feeding FFMA2 directly (no SHFL/MOV).
//     Last y slice: angle expansion.
// ---------------------------------------------------------------------------
__global__ void __launch_bounds__(256, 2)
k_edge(const int* __restrict__ ei, const float* __restrict__ ea,
       float* __restrict__ out, int E, int N) {
    int lane = threadIdx.x & 31;
    int w = blockIdx.x * (blockDim.x >> 5) + (threadIdx.x >> 5);
    int wpc = gridDim.x * (blockDim.x >> 5);

    if (blockIdx.y == SEGS) {
        // ---- angle expansion: out[j,:] += cnt*aA[s] + ts*aB[s] ----
        int ns = g_nseg_a;
        for (int j = w; j < N; j += wpc) {
            float acc = 0.0f;
            for (int s = 0; s < ns; s++) {
                float c = g_cnt[s * NMAX + j];
                if (c != 0.0f) {
                    float ts = g_ts[s * NMAX + j];
                    acc = fmaf(c, g_aA[s * 32 + lane], acc);
                    acc = fmaf(ts, g_aB[s * 32 + lane], acc);
                }
            }
            if (acc != 0.0f) atomicAdd(out + j * 32 + lane, acc);
        }
        return;
    }

    int s = blockIdx.y;
    if (s >= g_nseg_e) return;
    int cnt = g_ecnt[s];
    if (w * 2 >= cnt) return;

    // per-segment packed {A,B} table into registers (64 regs)
    unsigned long long ab[32];
    const unsigned long long* ABp = g_AB + s * 1024 + lane;
    #pragma unroll
    for (int i = 0; i < 32; i++) ab[i] = ABp[i * 32];

    const int* buck = g_ebuck + s * EMAX;
    int stride = wpc * 2;
    for (int idx = w * 2; idx < cnt; idx += stride) {
        bool has1 = (idx + 1 < cnt);
        int e0 = __ldg(buck + idx);
        int e1 = has1 ? __ldg(buck + idx + 1) : e0;
        float t0 = __ldg(ea + e0), t1 = __ldg(ea + e1);
        int r0 = __ldg(ei + e0), r1 = __ldg(ei + e1);
        int c0 = __ldg(ei + E + e0), c1 = __ldg(ei + E + e1);
        const ulonglong2* __restrict__ xd0 = (const ulonglong2*)(g_xdup + c0 * 64);
        const ulonglong2* __restrict__ xd1 = (const ulonglong2*)(g_xdup + c1 * 64);

        // 4 independent FFMA2 chains: (edge0 even/odd, edge1 even/odd)
        unsigned long long a0e = 0ull, a0o = 0ull, a1e = 0ull, a1o = 0ull;
        #pragma unroll
        for (int k = 0; k < 16; k++) {
            ulonglong2 v0 = xd0[k];   // uniform LDG.128: {x2k,x2k},{x2k+1,x2k+1}
            ulonglong2 v1 = xd1[k];
            asm("fma.rn.f32x2 %0, %1, %2, %0;" : "+l"(a0e) : "l"(v0.x), "l"(ab[2 * k]));
            asm("fma.rn.f32x2 %0, %1, %2, %0;" : "+l"(a0o) : "l"(v0.y), "l"(ab[2 * k + 1]));
            asm("fma.rn.f32x2 %0, %1, %2, %0;" : "+l"(a1e) : "l"(v1.x), "l"(ab[2 * k]));
            asm("fma.rn.f32x2 %0, %1, %2, %0;" : "+l"(a1o) : "l"(v1.y), "l"(ab[2 * k + 1]));
        }
        asm("add.rn.f32x2 %0, %0, %1;" : "+l"(a0e) : "l"(a0o));
        asm("add.rn.f32x2 %0, %0, %1;" : "+l"(a1e) : "l"(a1o));
        float cA, cB;
        asm("mov.b64 {%0, %1}, %2;" : "=f"(cA), "=f"(cB) : "l"(a0e));
        atomicAdd(out + r0 * 32 + lane, fmaf(t0, cB, cA));
        if (has1) {
            asm("mov.b64 {%0, %1}, %2;" : "=f"(cA), "=f"(cB) : "l"(a1e));
            atomicAdd(out + r1 * 32 + lane, fmaf(t1, cB, cA));
        }
    }
}

// ---------------------------------------------------------------------------
extern "C" void kernel_launch(void* const* d_in, const int* in_sizes, int n_in,
                              void* d_out, int out_size) {
    const float* x   = (const float*)d_in[0];
    const int*   ei  = (const int*)d_in[1];
    const float* ea  = (const float*)d_in[2];
    const int*   ai  = (const int*)d_in[3];
    const float* ang = (const float*)d_in[4];
    const float* eW1 = (const float*)d_in[5];
    const float* eb1 = (const float*)d_in[6];
    const float* eW2 = (const float*)d_in[7];
    const float* eb2 = (const float*)d_in[8];
    const float* aW1 = (const float*)d_in[9];
    const float* ab1 = (const float*)d_in[10];
    const float* aW2 = (const float*)d_in[11];
    const float* ab2 = (const float*)d_in[12];
    float* out = (float*)d_out;

    int N = in_sizes[0] / CH;
    int E = in_sizes[1] / 2;
    int A = in_sizes[3] / 3;

    k_pre<<<1, 64>>>(eW1, eb1, aW1, ab1);
    k_setup<<<SEGS + 1 + 512, 256>>>(eW1, eb1, eW2, eb2, aW1, ab1, aW2, ab2, out, N);
    int work = E > A ? E : A;
    if (work < N * 8) work = N * 8;      // cover x-dup writes too
    int fb = (work + 255) / 256;
    k_front<<<fb, 256>>>(ei, ea, ai, ang, x, E, A, N);
    dim3 ge(256, SEGS + 1);
    k_edge<<<ge, 256>>>(ei, ea, out, E, N);
}

// round 5
// speedup vs baseline: 1.3180x; 1.3180x over previous
#include <cuda_runtime.h>

#define CH 32
#define SEGS 33
#define NMAX 50000
#define EMAX 200000
#define FULL 0xffffffffu
#define NBLK 740
#define NWARP (NBLK * 4)

// ---- device-global scratch ----
__device__ float g_bp_e[32], g_bp_a[32];          // compacted breakpoints, sentinel 2.0
__device__ float g_trep_e[SEGS], g_trep_a[SEGS];  // per-segment representative t
__device__ int   g_nseg_e, g_nseg_a;              // effective segment counts
__device__ unsigned long long g_AB[SEGS * 1024];  // (s,i,lane) packed {A,B} float2
__device__ float g_aA[SEGS * 32], g_aB[SEGS * 32];
__device__ int   g_ecnt[SEGS];                    // per-segment edge count / cursor
__device__ __align__(16) int4 g_ebuckp[SEGS * EMAX]; // packed {row, col, t_bits, 0}
__device__ __align__(16) float g_cnt[SEGS * NMAX];
__device__ __align__(16) float g_ts[SEGS * NMAX];

// ---------------------------------------------------------------------------
// K1: compact breakpoints to (0,1) via parallel rank sort. Warp0=edge, warp1=angle.
// ---------------------------------------------------------------------------
__global__ void k_pre(const float* __restrict__ eW1, const float* __restrict__ eb1,
                      const float* __restrict__ aW1, const float* __restrict__ ab1) {
    __shared__ float sorted[2][33];
    int warp = threadIdx.x >> 5, lane = threadIdx.x & 31;
    if (threadIdx.x < SEGS) g_ecnt[threadIdx.x] = 0;
    if (warp > 1) return;

    const float* W = (warp == 0) ? eW1 : aW1;
    const float* B = (warp == 0) ? eb1 : ab1;
    float w = W[lane], b = B[lane];
    float p = (w != 0.0f) ? (-b / w) : -1.0f;
    bool valid = (p > 0.0f && p < 1.0f);
    unsigned vm = __ballot_sync(FULL, valid);
    int c = __popc(vm);

    int rank = 0;
    #pragma unroll
    for (int i = 0; i < 32; i++) {
        float pi = __shfl_sync(FULL, p, i);
        bool vi = (vm >> i) & 1;
        if (vi && (pi < p || (pi == p && i < lane))) rank++;
    }
    if (valid) sorted[warp][rank] = p;
    __syncwarp();

    float bpv = (lane < c) ? sorted[warp][lane] : 2.0f;
    if (warp == 0) g_bp_e[lane] = bpv; else g_bp_a[lane] = bpv;
    if (lane == 0) { if (warp == 0) g_nseg_e = c + 1; else g_nseg_a = c + 1; }

    for (int s = lane; s <= c; s += 32) {
        float lo = (s == 0) ? 0.0f : sorted[warp][s - 1];
        float hi = (s == c) ? 1.0f : sorted[warp][s];
        float tr = 0.5f * (lo + hi);
        if (warp == 0) g_trep_e[s] = tr; else g_trep_a[s] = tr;
    }
}

// ---------------------------------------------------------------------------
// K2: table build (blocks 0..SEGS) + vectorized zeroing (remaining blocks)
// ---------------------------------------------------------------------------
__global__ void k_setup(const float* __restrict__ eW1, const float* __restrict__ eb1,
                        const float* __restrict__ eW2, const float* __restrict__ eb2,
                        const float* __restrict__ aW1, const float* __restrict__ ab1,
                        const float* __restrict__ aW2, const float* __restrict__ ab2,
                        float* __restrict__ out, int N) {
    int blk = blockIdx.x;
    if (blk < SEGS) {
        int s = blk;
        if (s >= g_nseg_e) return;
        __shared__ float w1[32], b1[32];
        if (threadIdx.x < 32) { w1[threadIdx.x] = eW1[threadIdx.x]; b1[threadIdx.x] = eb1[threadIdx.x]; }
        __syncthreads();
        float trep = g_trep_e[s];
        float* ABf = (float*)g_AB;
        for (int io = threadIdx.x; io < 1024; io += blockDim.x) {
            float a = eb2[io], b = 0.0f;
            #pragma unroll
            for (int k = 0; k < 32; k++) {
                if (w1[k] * trep + b1[k] > 0.0f) {
                    float w2 = eW2[k * 1024 + io];
                    a = fmaf(b1[k], w2, a);
                    b = fmaf(w1[k], w2, b);
                }
            }
            int i = io >> 5, o = io & 31;
            int base = (((s * 32 + i) * 32) + o) * 2;
            ABf[base + 0] = a;
            ABf[base + 1] = b;
        }
    } else if (blk == SEGS) {
        int ns = g_nseg_a;
        for (int idx = threadIdx.x; idx < ns * 32; idx += blockDim.x) {
            int s2 = idx >> 5, o = idx & 31;
            float trep = g_trep_a[s2];
            float a = ab2[o], b = 0.0f;
            #pragma unroll
            for (int k = 0; k < 32; k++) {
                float w = aW1[k], bb = ab1[k];
                if (w * trep + bb > 0.0f) {
                    float w2 = aW2[k * 32 + o];
                    a = fmaf(bb, w2, a);
                    b = fmaf(w, w2, b);
                }
            }
            g_aA[idx] = a;
            g_aB[idx] = b;
        }
    } else {
        float4 z = make_float4(0.f, 0.f, 0.f, 0.f);
        long no = (long)N * 8;
        long nc = (long)g_nseg_a * (NMAX / 4);
        long nb = (long)gridDim.x - SEGS - 1;
        long gid = (long)(blk - SEGS - 1) * blockDim.x + threadIdx.x;
        long stride = nb * blockDim.x;
        float4* o4 = (float4*)out;
        float4* c4 = (float4*)g_cnt;
        float4* t4 = (float4*)g_ts;
        for (long i = gid; i < no; i += stride) o4[i] = z;
        for (long i = gid; i < nc; i += stride) { c4[i] = z; t4[i] = z; }
    }
}

// ---------------------------------------------------------------------------
// K3: front pass — packed edge bucketing (warp-aggregated) + angle scatter
// ---------------------------------------------------------------------------
__global__ void k_front(const int* __restrict__ ei, const float* __restrict__ ea,
                        const int* __restrict__ ai, const float* __restrict__ ang,
                        int E, int A) {
    __shared__ float sbe[32], sba[32];
    if (threadIdx.x < 32) { sbe[threadIdx.x] = g_bp_e[threadIdx.x]; sba[threadIdx.x] = g_bp_a[threadIdx.x]; }
    __syncthreads();
    int i = blockIdx.x * blockDim.x + threadIdx.x;
    int lane = threadIdx.x & 31;

    bool valid = (i < E);
    float t = valid ? __ldg(ea + i) : 0.0f;
    int r = valid ? __ldg(ei + i) : 0;
    int c = valid ? __ldg(ei + E + i) : 0;
    int seg = 0;
    #pragma unroll
    for (int k = 0; k < 32; k++) seg += (sbe[k] <= t) ? 1 : 0;
    int ns = g_nseg_e;
    for (int s = 0; s < ns; s++) {
        unsigned mask = __ballot_sync(FULL, valid && (seg == s));
        if (mask) {
            int leader = __ffs(mask) - 1;
            int base = 0;
            if (lane == leader) base = atomicAdd(&g_ecnt[s], __popc(mask));
            base = __shfl_sync(FULL, base, leader);
            if (valid && seg == s) {
                int pos = base + __popc(mask & ((1u << lane) - 1u));
                g_ebuckp[s * EMAX + pos] = make_int4(r, c, __float_as_int(t), 0);
            }
        }
    }

    if (i < A) {
        float ta = __ldg(ang + i);
        int j = __ldg(ai + A + i);   // angle_index[1] = center node
        int sa = 0;
        #pragma unroll
        for (int k = 0; k < 32; k++) sa += (sba[k] <= ta) ? 1 : 0;
        atomicAdd(&g_cnt[sa * NMAX + j], 1.0f);
        atomicAdd(&g_ts[sa * NMAX + j], ta);
    }
}

// ---------------------------------------------------------------------------
// K4: persistent kernel. Edge branch: warp per 2 edges, register A/B table,
//     x broadcast via SMEM-staged LDS.128 (no SHFL, no uniform LDG stream).
//     Then angle expansion.
// ---------------------------------------------------------------------------
__global__ void __launch_bounds__(128, 5)
k_edge(const float* __restrict__ x, float* __restrict__ out, int N) {
    __shared__ __align__(16) float stage[4][128];
    int lane = threadIdx.x & 31;
    int wi = threadIdx.x >> 5;
    int gw = blockIdx.x * 4 + wi;

    int ns = g_nseg_e;
    for (int s = 0; s < ns; s++) {
        int cnt = g_ecnt[s];
        if (gw * 2 >= cnt) continue;

        // per-segment packed {A,B} table into registers (64 regs)
        unsigned long long ab[32];
        const unsigned long long* ABp = g_AB + s * 1024 + lane;
        #pragma unroll
        for (int i = 0; i < 32; i++) ab[i] = ABp[i * 32];

        const int4* __restrict__ buck = g_ebuckp + s * EMAX;
        for (int idx = gw * 2; idx < cnt; idx += NWARP * 2) {
            bool has1 = (idx + 1 < cnt);
            int4 p0 = __ldg(buck + idx);                       // {row,col,t,0}
            int4 p1 = has1 ? __ldg(buck + idx + 1) : p0;
            float u0 = __ldg(x + p0.y * 32 + lane);            // coalesced
            float u1 = __ldg(x + p1.y * 32 + lane);
            __syncwarp();                                      // WAR vs prior iter reads
            ((float2*)stage[wi])[lane]      = make_float2(u0, u0);
            ((float2*)stage[wi])[32 + lane] = make_float2(u1, u1);
            __syncwarp();

            const ulonglong2* __restrict__ sv0 = (const ulonglong2*)stage[wi];
            const ulonglong2* __restrict__ sv1 = sv0 + 16;
            unsigned long long a0e = 0ull, a0o = 0ull, a1e = 0ull, a1o = 0ull;
            #pragma unroll
            for (int k = 0; k < 16; k++) {
                ulonglong2 v0 = sv0[k];   // LDS.128 broadcast: {x2k,x2k},{x2k+1,x2k+1}
                ulonglong2 v1 = sv1[k];
                asm("fma.rn.f32x2 %0, %1, %2, %0;" : "+l"(a0e) : "l"(v0.x), "l"(ab[2 * k]));
                asm("fma.rn.f32x2 %0, %1, %2, %0;" : "+l"(a0o) : "l"(v0.y), "l"(ab[2 * k + 1]));
                asm("fma.rn.f32x2 %0, %1, %2, %0;" : "+l"(a1e) : "l"(v1.x), "l"(ab[2 * k]));
                asm("fma.rn.f32x2 %0, %1, %2, %0;" : "+l"(a1o) : "l"(v1.y), "l"(ab[2 * k + 1]));
            }
            asm("add.rn.f32x2 %0, %0, %1;" : "+l"(a0e) : "l"(a0o));
            asm("add.rn.f32x2 %0, %0, %1;" : "+l"(a1e) : "l"(a1o));
            float cA, cB;
            asm("mov.b64 {%0, %1}, %2;" : "=f"(cA), "=f"(cB) : "l"(a0e));
            atomicAdd(out + p0.x * 32 + lane, fmaf(__int_as_float(p0.z), cB, cA));
            if (has1) {
                asm("mov.b64 {%0, %1}, %2;" : "=f"(cA), "=f"(cB) : "l"(a1e));
                atomicAdd(out + p1.x * 32 + lane, fmaf(__int_as_float(p1.z), cB, cA));
            }
        }
    }

    // ---- angle expansion: out[j,:] += cnt*aA[s] + ts*aB[s] ----
    int na = g_nseg_a;
    for (int j = gw; j < N; j += NWARP) {
        float acc = 0.0f;
        for (int s = 0; s < na; s++) {
            float c = g_cnt[s * NMAX + j];
            if (c != 0.0f) {
                float ts = g_ts[s * NMAX + j];
                acc = fmaf(c, g_aA[s * 32 + lane], acc);
                acc = fmaf(ts, g_aB[s * 32 + lane], acc);
            }
        }
        if (acc != 0.0f) atomicAdd(out + j * 32 + lane, acc);
    }
}

// ---------------------------------------------------------------------------
extern "C" void kernel_launch(void* const* d_in, const int* in_sizes, int n_in,
                              void* d_out, int out_size) {
    const float* x   = (const float*)d_in[0];
    const int*   ei  = (const int*)d_in[1];
    const float* ea  = (const float*)d_in[2];
    const int*   ai  = (const int*)d_in[3];
    const float* ang = (const float*)d_in[4];
    const float* eW1 = (const float*)d_in[5];
    const float* eb1 = (const float*)d_in[6];
    const float* eW2 = (const float*)d_in[7];
    const float* eb2 = (const float*)d_in[8];
    const float* aW1 = (const float*)d_in[9];
    const float* ab1 = (const float*)d_in[10];
    const float* aW2 = (const float*)d_in[11];
    const float* ab2 = (const float*)d_in[12];
    float* out = (float*)d_out;

    int N = in_sizes[0] / CH;
    int E = in_sizes[1] / 2;
    int A = in_sizes[3] / 3;

    k_pre<<<1, 64>>>(eW1, eb1, aW1, ab1);
    k_setup<<<SEGS + 1 + 512, 256>>>(eW1, eb1, eW2, eb2, aW1, ab1, aW2, ab2, out, N);
    int fb = ((E > A ? E : A) + 255) / 256;
    k_front<<<fb, 256>>>(ei, ea, ai, ang, E, A);
    k_edge<<<NBLK, 128>>>(x, out, N);
}

// round 6
// speedup vs baseline: 1.5905x; 1.2067x over previous
#include <cuda_runtime.h>

#define CH 32
#define SEGS 33
#define NMAX 50000
#define EMAX 200000
#define FULL 0xffffffffu
#define NBLK 592
#define NWARP (NBLK * 4)

typedef unsigned long long ull;

// ---- device-global scratch ----
__device__ float g_bp_e[32], g_bp_a[32];          // compacted breakpoints
__device__ float g_trep_e[SEGS], g_trep_a[SEGS];  // per-segment representative t
__device__ int   g_nseg_e, g_nseg_a;              // effective segment counts
// per segment: [0,512) = PA pairs {A[2k][o],A[2k+1][o]}, [512,1024) = PB pairs
__device__ ull   g_AB[SEGS * 1024];
__device__ float g_aA[SEGS * 32], g_aB[SEGS * 32];
__device__ int   g_ecnt[SEGS];                    // per-segment edge count / cursor
__device__ __align__(16) int4 g_ebuckp[SEGS * EMAX]; // packed {row, col, t_bits, 0}
__device__ __align__(16) float g_cnt[SEGS * NMAX];
__device__ __align__(16) float g_ts[SEGS * NMAX];

// ---------------------------------------------------------------------------
// K1: compact breakpoints to (0,1) via parallel rank sort. Warp0=edge, warp1=angle.
// ---------------------------------------------------------------------------
__global__ void k_pre(const float* __restrict__ eW1, const float* __restrict__ eb1,
                      const float* __restrict__ aW1, const float* __restrict__ ab1) {
    __shared__ float sorted[2][33];
    int warp = threadIdx.x >> 5, lane = threadIdx.x & 31;
    if (threadIdx.x < SEGS) g_ecnt[threadIdx.x] = 0;
    if (warp > 1) return;

    const float* W = (warp == 0) ? eW1 : aW1;
    const float* B = (warp == 0) ? eb1 : ab1;
    float w = W[lane], b = B[lane];
    float p = (w != 0.0f) ? (-b / w) : -1.0f;
    bool valid = (p > 0.0f && p < 1.0f);
    unsigned vm = __ballot_sync(FULL, valid);
    int c = __popc(vm);

    int rank = 0;
    #pragma unroll
    for (int i = 0; i < 32; i++) {
        float pi = __shfl_sync(FULL, p, i);
        bool vi = (vm >> i) & 1;
        if (vi && (pi < p || (pi == p && i < lane))) rank++;
    }
    if (valid) sorted[warp][rank] = p;
    __syncwarp();

    float bpv = (lane < c) ? sorted[warp][lane] : 2.0f;
    if (warp == 0) g_bp_e[lane] = bpv; else g_bp_a[lane] = bpv;
    if (lane == 0) { if (warp == 0) g_nseg_e = c + 1; else g_nseg_a = c + 1; }

    for (int s = lane; s <= c; s += 32) {
        float lo = (s == 0) ? 0.0f : sorted[warp][s - 1];
        float hi = (s == c) ? 1.0f : sorted[warp][s];
        float tr = 0.5f * (lo + hi);
        if (warp == 0) g_trep_e[s] = tr; else g_trep_a[s] = tr;
    }
}

// ---------------------------------------------------------------------------
// K2: table build (blocks 0..SEGS) + vectorized zeroing (remaining blocks)
// ---------------------------------------------------------------------------
__global__ void k_setup(const float* __restrict__ eW1, const float* __restrict__ eb1,
                        const float* __restrict__ eW2, const float* __restrict__ eb2,
                        const float* __restrict__ aW1, const float* __restrict__ ab1,
                        const float* __restrict__ aW2, const float* __restrict__ ab2,
                        float* __restrict__ out, int N) {
    int blk = blockIdx.x;
    if (blk < SEGS) {
        int s = blk;
        if (s >= g_nseg_e) return;
        __shared__ float w1[32], b1[32];
        if (threadIdx.x < 32) { w1[threadIdx.x] = eW1[threadIdx.x]; b1[threadIdx.x] = eb1[threadIdx.x]; }
        __syncthreads();
        float trep = g_trep_e[s];
        float* ABf = (float*)g_AB;
        for (int io = threadIdx.x; io < 1024; io += blockDim.x) {
            float a = eb2[io], b = 0.0f;
            #pragma unroll
            for (int k = 0; k < 32; k++) {
                if (w1[k] * trep + b1[k] > 0.0f) {
                    float w2 = eW2[k * 1024 + io];
                    a = fmaf(b1[k], w2, a);
                    b = fmaf(w1[k], w2, b);
                }
            }
            int i = io >> 5, o = io & 31;
            // pair layout: PA[kk][o] = {A[2kk][o], A[2kk+1][o]}
            int pa = s * 2048 + (i >> 1) * 64 + o * 2 + (i & 1);
            ABf[pa] = a;
            ABf[pa + 1024] = b;
        }
    } else if (blk == SEGS) {
        int ns = g_nseg_a;
        for (int idx = threadIdx.x; idx < ns * 32; idx += blockDim.x) {
            int s2 = idx >> 5, o = idx & 31;
            float trep = g_trep_a[s2];
            float a = ab2[o], b = 0.0f;
            #pragma unroll
            for (int k = 0; k < 32; k++) {
                float w = aW1[k], bb = ab1[k];
                if (w * trep + bb > 0.0f) {
                    float w2 = aW2[k * 32 + o];
                    a = fmaf(bb, w2, a);
                    b = fmaf(w, w2, b);
                }
            }
            g_aA[idx] = a;
            g_aB[idx] = b;
        }
    } else {
        float4 z = make_float4(0.f, 0.f, 0.f, 0.f);
        long no = (long)N * 8;
        long nc = (long)g_nseg_a * (NMAX / 4);
        long nb = (long)gridDim.x - SEGS - 1;
        long gid = (long)(blk - SEGS - 1) * blockDim.x + threadIdx.x;
        long stride = nb * blockDim.x;
        float4* o4 = (float4*)out;
        float4* c4 = (float4*)g_cnt;
        float4* t4 = (float4*)g_ts;
        for (long i = gid; i < no; i += stride) o4[i] = z;
        for (long i = gid; i < nc; i += stride) { c4[i] = z; t4[i] = z; }
    }
}

// ---------------------------------------------------------------------------
// K3: front pass — packed edge bucketing (warp-aggregated) + angle scatter.
//     Segment search loops bounded by the (small) dynamic breakpoint count.
// ---------------------------------------------------------------------------
__global__ void k_front(const int* __restrict__ ei, const float* __restrict__ ea,
                        const int* __restrict__ ai, const float* __restrict__ ang,
                        int E, int A) {
    __shared__ float sbe[32], sba[32];
    if (threadIdx.x < 32) { sbe[threadIdx.x] = g_bp_e[threadIdx.x]; sba[threadIdx.x] = g_bp_a[threadIdx.x]; }
    __syncthreads();
    int i = blockIdx.x * blockDim.x + threadIdx.x;
    int lane = threadIdx.x & 31;
    int nbe = g_nseg_e - 1;   // # breakpoints
    int nba = g_nseg_a - 1;

    bool valid = (i < E);
    float t = valid ? __ldg(ea + i) : 0.0f;
    int r = valid ? __ldg(ei + i) : 0;
    int c = valid ? __ldg(ei + E + i) : 0;
    int seg = 0;
    for (int k = 0; k < nbe; k++) seg += (sbe[k] <= t) ? 1 : 0;
    int ns = nbe + 1;
    for (int s = 0; s < ns; s++) {
        unsigned mask = __ballot_sync(FULL, valid && (seg == s));
        if (mask) {
            int leader = __ffs(mask) - 1;
            int base = 0;
            if (lane == leader) base = atomicAdd(&g_ecnt[s], __popc(mask));
            base = __shfl_sync(FULL, base, leader);
            if (valid && seg == s) {
                int pos = base + __popc(mask & ((1u << lane) - 1u));
                g_ebuckp[s * EMAX + pos] = make_int4(r, c, __float_as_int(t), 0);
            }
        }
    }

    if (i < A) {
        float ta = __ldg(ang + i);
        int j = __ldg(ai + A + i);   // angle_index[1] = center node
        int sa = 0;
        for (int k = 0; k < nba; k++) sa += (sba[k] <= ta) ? 1 : 0;
        atomicAdd(&g_cnt[sa * NMAX + j], 1.0f);
        atomicAdd(&g_ts[sa * NMAX + j], ta);
    }
}

// ---------------------------------------------------------------------------
// K4: persistent kernel. Edge branch: warp per 4 edges/iter, re-paired register
//     table so raw (non-duplicated) LDS.128 broadcasts feed FFMA2 directly.
//     acc.lo = even-i partial, acc.hi = odd-i partial; summed at the end.
//     Then angle expansion.
// ---------------------------------------------------------------------------
__global__ void __launch_bounds__(128, 4)
k_edge(const float* __restrict__ x, float* __restrict__ out, int N) {
    __shared__ __align__(16) float stage[4][128];   // [warp][4 edges * 32 floats]
    int lane = threadIdx.x & 31;
    int wi = threadIdx.x >> 5;
    int gw = blockIdx.x * 4 + wi;
    int q_my = lane >> 3;       // which of the 4 staged edges this lane loads
    int sub = lane & 7;         // which float4 of that edge's row

    int ns = g_nseg_e;
    for (int s = 0; s < ns; s++) {
        int cnt = g_ecnt[s];
        int idx = gw * 4;
        if (idx >= cnt) continue;

        // re-paired table: abA[kk] = {A[2kk][o], A[2kk+1][o]}, abB likewise
        ull abA[16], abB[16];
        const ull* T = g_AB + s * 1024;
        #pragma unroll
        for (int k = 0; k < 16; k++) {
            abA[k] = T[k * 32 + lane];
            abB[k] = T[512 + k * 32 + lane];
        }

        const int4* __restrict__ buck = g_ebuckp + s * EMAX;

        // prefetch first batch
        int ei0 = idx + q_my; if (ei0 > cnt - 1) ei0 = cnt - 1;
        int4 pm = __ldg(buck + ei0);
        float4 xf = __ldg((const float4*)(x + pm.y * 32) + sub);

        while (idx < cnt) {
            ((float4*)stage[wi])[lane] = xf;
            __syncwarp();
            int cur = idx;
            idx += NWARP * 4;
            if (idx < cnt) {   // prefetch next batch (overlaps compute below)
                int ei = idx + q_my; if (ei > cnt - 1) ei = cnt - 1;
                pm = __ldg(buck + ei);
                xf = __ldg((const float4*)(x + pm.y * 32) + sub);
            }

            #pragma unroll
            for (int q = 0; q < 4; q++) {
                if (cur + q < cnt) {
                    int4 pq = __ldg(buck + cur + q);   // uniform L1-hit
                    const ulonglong2* __restrict__ sv =
                        (const ulonglong2*)(stage[wi] + q * 32);
                    ull accA = 0ull, accB = 0ull;
                    #pragma unroll
                    for (int j = 0; j < 8; j++) {
                        ulonglong2 v = sv[j];   // LDS.128 broadcast {x4j..x4j+3}
                        asm("fma.rn.f32x2 %0, %1, %2, %0;" : "+l"(accA) : "l"(v.x), "l"(abA[2 * j]));
                        asm("fma.rn.f32x2 %0, %1, %2, %0;" : "+l"(accB) : "l"(v.x), "l"(abB[2 * j]));
                        asm("fma.rn.f32x2 %0, %1, %2, %0;" : "+l"(accA) : "l"(v.y), "l"(abA[2 * j + 1]));
                        asm("fma.rn.f32x2 %0, %1, %2, %0;" : "+l"(accB) : "l"(v.y), "l"(abB[2 * j + 1]));
                    }
                    float alo, ahi, blo, bhi;
                    asm("mov.b64 {%0, %1}, %2;" : "=f"(alo), "=f"(ahi) : "l"(accA));
                    asm("mov.b64 {%0, %1}, %2;" : "=f"(blo), "=f"(bhi) : "l"(accB));
                    float tq = __int_as_float(pq.z);
                    atomicAdd(out + pq.x * 32 + lane, fmaf(tq, blo + bhi, alo + ahi));
                }
            }
            __syncwarp();   // protect stage before next STS
        }
    }

    // ---- angle expansion: out[j,:] += cnt*aA[s] + ts*aB[s] ----
    int na = g_nseg_a;
    for (int j = gw; j < N; j += NWARP) {
        float acc = 0.0f;
        for (int s = 0; s < na; s++) {
            float c = g_cnt[s * NMAX + j];
            if (c != 0.0f) {
                float ts = g_ts[s * NMAX + j];
                acc = fmaf(c, g_aA[s * 32 + lane], acc);
                acc = fmaf(ts, g_aB[s * 32 + lane], acc);
            }
        }
        if (acc != 0.0f) atomicAdd(out + j * 32 + lane, acc);
    }
}

// ---------------------------------------------------------------------------
extern "C" void kernel_launch(void* const* d_in, const int* in_sizes, int n_in,
                              void* d_out, int out_size) {
    const float* x   = (const float*)d_in[0];
    const int*   ei  = (const int*)d_in[1];
    const float* ea  = (const float*)d_in[2];
    const int*   ai  = (const int*)d_in[3];
    const float* ang = (const float*)d_in[4];
    const float* eW1 = (const float*)d_in[5];
    const float* eb1 = (const float*)d_in[6];
    const float* eW2 = (const float*)d_in[7];
    const float* eb2 = (const float*)d_in[8];
    const float* aW1 = (const float*)d_in[9];
    const float* ab1 = (const float*)d_in[10];
    const float* aW2 = (const float*)d_in[11];
    const float* ab2 = (const float*)d_in[12];
    float* out = (float*)d_out;

    int N = in_sizes[0] / CH;
    int E = in_sizes[1] / 2;
    int A = in_sizes[3] / 3;

    k_pre<<<1, 64>>>(eW1, eb1, aW1, ab1);
    k_setup<<<SEGS + 1 + 512, 256>>>(eW1, eb1, eW2, eb2, aW1, ab1, aW2, ab2, out, N);
    int fb = ((E > A ? E : A) + 255) / 256;
    k_front<<<fb, 256>>>(ei, ea, ai, ang, E, A);
    k_edge<<<NBLK, 128>>>(x, out, N);
}

// round 7
// speedup vs baseline: 1.6885x; 1.0616x over previous
#include <cuda_runtime.h>

#define CH 32
#define SEGS 33
#define NMAX 50000
#define EMAX 200000
#define FULL 0xffffffffu
#define NBLK 592
#define NWARP (NBLK * 4)

typedef unsigned long long ull;

// ---- device-global scratch ----
__device__ float g_bp_e[32], g_bp_a[32];          // compacted breakpoints
__device__ float g_trep_e[SEGS], g_trep_a[SEGS];  // per-segment representative t
__device__ int   g_nseg_e, g_nseg_a;              // effective segment counts
// per segment: [0,512) = PA pairs {A[2k][o],A[2k+1][o]}, [512,1024) = PB pairs
__device__ ull   g_AB[SEGS * 1024];
__device__ float g_aA[SEGS * 32], g_aB[SEGS * 32];
__device__ int   g_ecnt[SEGS];                    // per-segment edge count / cursor
__device__ __align__(16) int4 g_ebuckp[SEGS * EMAX]; // packed {row, col, t_bits, 0}
__device__ __align__(16) float g_cnt[SEGS * NMAX];
__device__ __align__(16) float g_ts[SEGS * NMAX];

// ---------------------------------------------------------------------------
// K1: compact breakpoints to (0,1) via parallel rank sort. Warp0=edge, warp1=angle.
// ---------------------------------------------------------------------------
__global__ void k_pre(const float* __restrict__ eW1, const float* __restrict__ eb1,
                      const float* __restrict__ aW1, const float* __restrict__ ab1) {
    __shared__ float sorted[2][33];
    int warp = threadIdx.x >> 5, lane = threadIdx.x & 31;
    if (threadIdx.x < SEGS) g_ecnt[threadIdx.x] = 0;
    if (warp > 1) return;

    const float* W = (warp == 0) ? eW1 : aW1;
    const float* B = (warp == 0) ? eb1 : ab1;
    float w = W[lane], b = B[lane];
    float p = (w != 0.0f) ? (-b / w) : -1.0f;
    bool valid = (p > 0.0f && p < 1.0f);
    unsigned vm = __ballot_sync(FULL, valid);
    int c = __popc(vm);

    int rank = 0;
    #pragma unroll
    for (int i = 0; i < 32; i++) {
        float pi = __shfl_sync(FULL, p, i);
        bool vi = (vm >> i) & 1;
        if (vi && (pi < p || (pi == p && i < lane))) rank++;
    }
    if (valid) sorted[warp][rank] = p;
    __syncwarp();

    float bpv = (lane < c) ? sorted[warp][lane] : 2.0f;
    if (warp == 0) g_bp_e[lane] = bpv; else g_bp_a[lane] = bpv;
    if (lane == 0) { if (warp == 0) g_nseg_e = c + 1; else g_nseg_a = c + 1; }

    for (int s = lane; s <= c; s += 32) {
        float lo = (s == 0) ? 0.0f : sorted[warp][s - 1];
        float hi = (s == c) ? 1.0f : sorted[warp][s];
        float tr = 0.5f * (lo + hi);
        if (warp == 0) g_trep_e[s] = tr; else g_trep_a[s] = tr;
    }
}

// ---------------------------------------------------------------------------
// K2: table build (blocks 0..SEGS) + zeroing of angle accumulators
// ---------------------------------------------------------------------------
__global__ void k_setup(const float* __restrict__ eW1, const float* __restrict__ eb1,
                        const float* __restrict__ eW2, const float* __restrict__ eb2,
                        const float* __restrict__ aW1, const float* __restrict__ ab1,
                        const float* __restrict__ aW2, const float* __restrict__ ab2) {
    int blk = blockIdx.x;
    if (blk < SEGS) {
        int s = blk;
        if (s >= g_nseg_e) return;
        __shared__ float w1[32], b1[32];
        if (threadIdx.x < 32) { w1[threadIdx.x] = eW1[threadIdx.x]; b1[threadIdx.x] = eb1[threadIdx.x]; }
        __syncthreads();
        float trep = g_trep_e[s];
        float* ABf = (float*)g_AB;
        for (int io = threadIdx.x; io < 1024; io += blockDim.x) {
            float a = eb2[io], b = 0.0f;
            #pragma unroll
            for (int k = 0; k < 32; k++) {
                if (w1[k] * trep + b1[k] > 0.0f) {
                    float w2 = eW2[k * 1024 + io];
                    a = fmaf(b1[k], w2, a);
                    b = fmaf(w1[k], w2, b);
                }
            }
            int i = io >> 5, o = io & 31;
            // pair layout: PA[kk][o] = {A[2kk][o], A[2kk+1][o]}
            int pa = s * 2048 + (i >> 1) * 64 + o * 2 + (i & 1);
            ABf[pa] = a;
            ABf[pa + 1024] = b;
        }
    } else if (blk == SEGS) {
        int ns = g_nseg_a;
        for (int idx = threadIdx.x; idx < ns * 32; idx += blockDim.x) {
            int s2 = idx >> 5, o = idx & 31;
            float trep = g_trep_a[s2];
            float a = ab2[o], b = 0.0f;
            #pragma unroll
            for (int k = 0; k < 32; k++) {
                float w = aW1[k], bb = ab1[k];
                if (w * trep + bb > 0.0f) {
                    float w2 = aW2[k * 32 + o];
                    a = fmaf(bb, w2, a);
                    b = fmaf(w, w2, b);
                }
            }
            g_aA[idx] = a;
            g_aB[idx] = b;
        }
    } else {
        float4 z = make_float4(0.f, 0.f, 0.f, 0.f);
        long nc = (long)g_nseg_a * (NMAX / 4);
        long nb = (long)gridDim.x - SEGS - 1;
        long gid = (long)(blk - SEGS - 1) * blockDim.x + threadIdx.x;
        long stride = nb * blockDim.x;
        float4* c4 = (float4*)g_cnt;
        float4* t4 = (float4*)g_ts;
        for (long i = gid; i < nc; i += stride) { c4[i] = z; t4[i] = z; }
    }
}

// ---------------------------------------------------------------------------
// K3: front pass — packed edge bucketing (warp-aggregated) + angle scatter
// ---------------------------------------------------------------------------
__global__ void k_front(const int* __restrict__ ei, const float* __restrict__ ea,
                        const int* __restrict__ ai, const float* __restrict__ ang,
                        int E, int A) {
    __shared__ float sbe[32], sba[32];
    if (threadIdx.x < 32) { sbe[threadIdx.x] = g_bp_e[threadIdx.x]; sba[threadIdx.x] = g_bp_a[threadIdx.x]; }
    __syncthreads();
    int i = blockIdx.x * blockDim.x + threadIdx.x;
    int lane = threadIdx.x & 31;
    int nbe = g_nseg_e - 1;
    int nba = g_nseg_a - 1;

    bool valid = (i < E);
    float t = valid ? __ldg(ea + i) : 0.0f;
    int r = valid ? __ldg(ei + i) : 0;
    int c = valid ? __ldg(ei + E + i) : 0;
    int seg = 0;
    for (int k = 0; k < nbe; k++) seg += (sbe[k] <= t) ? 1 : 0;
    int ns = nbe + 1;
    for (int s = 0; s < ns; s++) {
        unsigned mask = __ballot_sync(FULL, valid && (seg == s));
        if (mask) {
            int leader = __ffs(mask) - 1;
            int base = 0;
            if (lane == leader) base = atomicAdd(&g_ecnt[s], __popc(mask));
            base = __shfl_sync(FULL, base, leader);
            if (valid && seg == s) {
                int pos = base + __popc(mask & ((1u << lane) - 1u));
                g_ebuckp[s * EMAX + pos] = make_int4(r, c, __float_as_int(t), 0);
            }
        }
    }

    if (i < A) {
        float ta = __ldg(ang + i);
        int j = __ldg(ai + A + i);
        int sa = 0;
        for (int k = 0; k < nba; k++) sa += (sba[k] <= ta) ? 1 : 0;
        atomicAdd(&g_cnt[sa * NMAX + j], 1.0f);
        atomicAdd(&g_ts[sa * NMAX + j], ta);
    }
}

// ---------------------------------------------------------------------------
// K3.5: angle expansion with PLAIN stores — initializes out (replaces zeroing,
//       removes all angle atomics). Must run before k_edge.
// ---------------------------------------------------------------------------
__global__ void k_angle(float* __restrict__ out, int N) {
    int j = (blockIdx.x * blockDim.x + threadIdx.x) >> 5;
    int lane = threadIdx.x & 31;
    if (j >= N) return;
    int na = g_nseg_a;
    float acc = 0.0f;
    for (int s = 0; s < na; s++) {
        float c = g_cnt[s * NMAX + j];
        if (c != 0.0f) {
            float ts = g_ts[s * NMAX + j];
            acc = fmaf(c, g_aA[s * 32 + lane], acc);
            acc = fmaf(ts, g_aB[s * 32 + lane], acc);
        }
    }
    out[j * 32 + lane] = acc;   // plain coalesced store: also the initializer
}

// ---------------------------------------------------------------------------
// K4: edge branch. Warp per 4 edges/iter, branchless, 8 interleaved FFMA2
//     chains, results staged to smem then flushed with red.global.add.v4.f32
//     (8 lanes per edge instead of 32).
// ---------------------------------------------------------------------------
__global__ void __launch_bounds__(128, 4)
k_edge(const float* __restrict__ x, float* __restrict__ out) {
    __shared__ __align__(16) float stage[4][128];   // [warp][4 edges * 32 x-floats]
    __shared__ __align__(16) float stres[4][128];   // [warp][4 edges * 32 results]
    int lane = threadIdx.x & 31;
    int wi = threadIdx.x >> 5;
    int gw = blockIdx.x * 4 + wi;
    int q_my = lane >> 3;
    int sub = lane & 7;

    int ns = g_nseg_e;
    for (int s = 0; s < ns; s++) {
        int cnt = g_ecnt[s];
        int idx = gw * 4;
        if (idx >= cnt) continue;

        ull abA[16], abB[16];
        const ull* T = g_AB + s * 1024;
        #pragma unroll
        for (int k = 0; k < 16; k++) {
            abA[k] = T[k * 32 + lane];
            abB[k] = T[512 + k * 32 + lane];
        }

        const int4* __restrict__ buck = g_ebuckp + s * EMAX;

        // prefetch first batch (this lane stages edge q_my's x row)
        int ep = idx + q_my; if (ep > cnt - 1) ep = cnt - 1;
        int4 pm = __ldg(buck + ep);
        float4 xf = __ldg((const float4*)(x + pm.y * 32) + sub);

        while (idx < cnt) {
            ((float4*)stage[wi])[lane] = xf;
            __syncwarp();
            int cur = idx;
            idx += NWARP * 4;
            if (idx < cnt) {
                int en = idx + q_my; if (en > cnt - 1) en = cnt - 1;
                pm = __ldg(buck + en);
                xf = __ldg((const float4*)(x + pm.y * 32) + sub);
            }

            // branchless clamped edge descriptors (uniform L1-hit loads)
            int m = cnt - 1;
            int4 p0 = __ldg(buck + cur);
            int4 p1 = __ldg(buck + (cur + 1 > m ? m : cur + 1));
            int4 p2 = __ldg(buck + (cur + 2 > m ? m : cur + 2));
            int4 p3 = __ldg(buck + (cur + 3 > m ? m : cur + 3));

            const ulonglong2* __restrict__ sv = (const ulonglong2*)stage[wi];
            ull aA0 = 0, aB0 = 0, aA1 = 0, aB1 = 0, aA2 = 0, aB2 = 0, aA3 = 0, aB3 = 0;
            #pragma unroll
            for (int j = 0; j < 8; j++) {
                ulonglong2 v0 = sv[j], v1 = sv[8 + j], v2 = sv[16 + j], v3 = sv[24 + j];
                asm("fma.rn.f32x2 %0, %1, %2, %0;" : "+l"(aA0) : "l"(v0.x), "l"(abA[2 * j]));
                asm("fma.rn.f32x2 %0, %1, %2, %0;" : "+l"(aB0) : "l"(v0.x), "l"(abB[2 * j]));
                asm("fma.rn.f32x2 %0, %1, %2, %0;" : "+l"(aA1) : "l"(v1.x), "l"(abA[2 * j]));
                asm("fma.rn.f32x2 %0, %1, %2, %0;" : "+l"(aB1) : "l"(v1.x), "l"(abB[2 * j]));
                asm("fma.rn.f32x2 %0, %1, %2, %0;" : "+l"(aA2) : "l"(v2.x), "l"(abA[2 * j]));
                asm("fma.rn.f32x2 %0, %1, %2, %0;" : "+l"(aB2) : "l"(v2.x), "l"(abB[2 * j]));
                asm("fma.rn.f32x2 %0, %1, %2, %0;" : "+l"(aA3) : "l"(v3.x), "l"(abA[2 * j]));
                asm("fma.rn.f32x2 %0, %1, %2, %0;" : "+l"(aB3) : "l"(v3.x), "l"(abB[2 * j]));
                asm("fma.rn.f32x2 %0, %1, %2, %0;" : "+l"(aA0) : "l"(v0.y), "l"(abA[2 * j + 1]));
                asm("fma.rn.f32x2 %0, %1, %2, %0;" : "+l"(aB0) : "l"(v0.y), "l"(abB[2 * j + 1]));
                asm("fma.rn.f32x2 %0, %1, %2, %0;" : "+l"(aA1) : "l"(v1.y), "l"(abA[2 * j + 1]));
                asm("fma.rn.f32x2 %0, %1, %2, %0;" : "+l"(aB1) : "l"(v1.y), "l"(abB[2 * j + 1]));
                asm("fma.rn.f32x2 %0, %1, %2, %0;" : "+l"(aA2) : "l"(v2.y), "l"(abA[2 * j + 1]));
                asm("fma.rn.f32x2 %0, %1, %2, %0;" : "+l"(aB2) : "l"(v2.y), "l"(abB[2 * j + 1]));
                asm("fma.rn.f32x2 %0, %1, %2, %0;" : "+l"(aA3) : "l"(v3.y), "l"(abA[2 * j + 1]));
                asm("fma.rn.f32x2 %0, %1, %2, %0;" : "+l"(aB3) : "l"(v3.y), "l"(abB[2 * j + 1]));
            }
            float alo, ahi, blo, bhi;
            asm("mov.b64 {%0, %1}, %2;" : "=f"(alo), "=f"(ahi) : "l"(aA0));
            asm("mov.b64 {%0, %1}, %2;" : "=f"(blo), "=f"(bhi) : "l"(aB0));
            stres[wi][lane] = fmaf(__int_as_float(p0.z), blo + bhi, alo + ahi);
            asm("mov.b64 {%0, %1}, %2;" : "=f"(alo), "=f"(ahi) : "l"(aA1));
            asm("mov.b64 {%0, %1}, %2;" : "=f"(blo), "=f"(bhi) : "l"(aB1));
            stres[wi][32 + lane] = fmaf(__int_as_float(p1.z), blo + bhi, alo + ahi);
            asm("mov.b64 {%0, %1}, %2;" : "=f"(alo), "=f"(ahi) : "l"(aA2));
            asm("mov.b64 {%0, %1}, %2;" : "=f"(blo), "=f"(bhi) : "l"(aB2));
            stres[wi][64 + lane] = fmaf(__int_as_float(p2.z), blo + bhi, alo + ahi);
            asm("mov.b64 {%0, %1}, %2;" : "=f"(alo), "=f"(ahi) : "l"(aA3));
            asm("mov.b64 {%0, %1}, %2;" : "=f"(blo), "=f"(bhi) : "l"(aB3));
            stres[wi][96 + lane] = fmaf(__int_as_float(p3.z), blo + bhi, alo + ahi);
            __syncwarp();

            // flush: 8 lanes per edge, red.global.add.v4.f32
            int row = (q_my == 0) ? p0.x : (q_my == 1) ? p1.x : (q_my == 2) ? p2.x : p3.x;
            if (cur + q_my < cnt) {
                float4 v = ((const float4*)stres[wi])[lane];
                float* dst = out + row * 32 + sub * 4;
                asm volatile("red.global.add.v4.f32 [%0], {%1, %2, %3, %4};"
                             :: "l"(dst), "f"(v.x), "f"(v.y), "f"(v.z), "f"(v.w)
                             : "memory");
            }
            __syncwarp();   // protect stage/stres before next iteration's writes
        }
    }
}

// ---------------------------------------------------------------------------
extern "C" void kernel_launch(void* const* d_in, const int* in_sizes, int n_in,
                              void* d_out, int out_size) {
    const float* x   = (const float*)d_in[0];
    const int*   ei  = (const int*)d_in[1];
    const float* ea  = (const float*)d_in[2];
    const int*   ai  = (const int*)d_in[3];
    const float* ang = (const float*)d_in[4];
    const float* eW1 = (const float*)d_in[5];
    const float* eb1 = (const float*)d_in[6];
    const float* eW2 = (const float*)d_in[7];
    const float* eb2 = (const float*)d_in[8];
    const float* aW1 = (const float*)d_in[9];
    const float* ab1 = (const float*)d_in[10];
    const float* aW2 = (const float*)d_in[11];
    const float* ab2 = (const float*)d_in[12];
    float* out = (float*)d_out;

    int N = in_sizes[0] / CH;
    int E = in_sizes[1] / 2;
    int A = in_sizes[3] / 3;

    k_pre<<<1, 64>>>(eW1, eb1, aW1, ab1);
    k_setup<<<SEGS + 1 + 256, 256>>>(eW1, eb1, eW2, eb2, aW1, ab1, aW2, ab2);
    int fb = ((E > A ? E : A) + 255) / 256;
    k_front<<<fb, 256>>>(ei, ea, ai, ang, E, A);
    k_angle<<<(N + 3) / 4, 128>>>(out, N);
    k_edge<<<NBLK, 128>>>(x, out);
}

// round 8
// speedup vs baseline: 1.8048x; 1.0689x over previous
#include <cuda_runtime.h>

#define CH 32
#define SEGS 33
#define NMAX 50000
#define EMAX 200000
#define FULL 0xffffffffu
#define NBLK 592
#define NWARP (NBLK * 4)
#define ACH 8

typedef unsigned long long ull;

// ---- device-global scratch ----
__device__ float g_bp_e[32], g_bp_a[32];          // compacted breakpoints
__device__ float g_trep_e[SEGS], g_trep_a[SEGS];  // per-segment representative t
__device__ int   g_nseg_e, g_nseg_a;              // effective segment counts
// per segment: [0,512) = PA pairs {A[2k][o],A[2k+1][o]}, [512,1024) = PB pairs
__device__ ull   g_AB[SEGS * 1024];
__device__ float g_aA[SEGS * 32], g_aB[SEGS * 32];
__device__ int   g_ecnt[SEGS];                    // per-segment edge count / cursor
__device__ __align__(16) int4 g_ebuckp[SEGS * EMAX]; // packed {row, col, t_bits, 0}
__device__ __align__(16) float2 g_cts[SEGS * NMAX];  // (count, sum_t) per (seg, node)

// ---------------------------------------------------------------------------
// K1: compact breakpoints to (0,1) via parallel rank sort. Warp0=edge, warp1=angle.
// ---------------------------------------------------------------------------
__global__ void k_pre(const float* __restrict__ eW1, const float* __restrict__ eb1,
                      const float* __restrict__ aW1, const float* __restrict__ ab1) {
    __shared__ float sorted[2][33];
    int warp = threadIdx.x >> 5, lane = threadIdx.x & 31;
    if (threadIdx.x < SEGS) g_ecnt[threadIdx.x] = 0;
    if (warp > 1) return;

    const float* W = (warp == 0) ? eW1 : aW1;
    const float* B = (warp == 0) ? eb1 : ab1;
    float w = W[lane], b = B[lane];
    float p = (w != 0.0f) ? (-b / w) : -1.0f;
    bool valid = (p > 0.0f && p < 1.0f);
    unsigned vm = __ballot_sync(FULL, valid);
    int c = __popc(vm);

    int rank = 0;
    #pragma unroll
    for (int i = 0; i < 32; i++) {
        float pi = __shfl_sync(FULL, p, i);
        bool vi = (vm >> i) & 1;
        if (vi && (pi < p || (pi == p && i < lane))) rank++;
    }
    if (valid) sorted[warp][rank] = p;
    __syncwarp();

    float bpv = (lane < c) ? sorted[warp][lane] : 2.0f;
    if (warp == 0) g_bp_e[lane] = bpv; else g_bp_a[lane] = bpv;
    if (lane == 0) { if (warp == 0) g_nseg_e = c + 1; else g_nseg_a = c + 1; }

    for (int s = lane; s <= c; s += 32) {
        float lo = (s == 0) ? 0.0f : sorted[warp][s - 1];
        float hi = (s == c) ? 1.0f : sorted[warp][s];
        float tr = 0.5f * (lo + hi);
        if (warp == 0) g_trep_e[s] = tr; else g_trep_a[s] = tr;
    }
}

// ---------------------------------------------------------------------------
// K2: table build (blocks 0..SEGS) + zeroing of angle accumulators
// ---------------------------------------------------------------------------
__global__ void k_setup(const float* __restrict__ eW1, const float* __restrict__ eb1,
                        const float* __restrict__ eW2, const float* __restrict__ eb2,
                        const float* __restrict__ aW1, const float* __restrict__ ab1,
                        const float* __restrict__ aW2, const float* __restrict__ ab2) {
    int blk = blockIdx.x;
    if (blk < SEGS) {
        int s = blk;
        if (s >= g_nseg_e) return;
        __shared__ float w1[32], b1[32];
        if (threadIdx.x < 32) { w1[threadIdx.x] = eW1[threadIdx.x]; b1[threadIdx.x] = eb1[threadIdx.x]; }
        __syncthreads();
        float trep = g_trep_e[s];
        float* ABf = (float*)g_AB;
        for (int io = threadIdx.x; io < 1024; io += blockDim.x) {
            float a = eb2[io], b = 0.0f;
            #pragma unroll
            for (int k = 0; k < 32; k++) {
                if (w1[k] * trep + b1[k] > 0.0f) {
                    float w2 = eW2[k * 1024 + io];
                    a = fmaf(b1[k], w2, a);
                    b = fmaf(w1[k], w2, b);
                }
            }
            int i = io >> 5, o = io & 31;
            int pa = s * 2048 + (i >> 1) * 64 + o * 2 + (i & 1);
            ABf[pa] = a;
            ABf[pa + 1024] = b;
        }
    } else if (blk == SEGS) {
        int ns = g_nseg_a;
        for (int idx = threadIdx.x; idx < ns * 32; idx += blockDim.x) {
            int s2 = idx >> 5, o = idx & 31;
            float trep = g_trep_a[s2];
            float a = ab2[o], b = 0.0f;
            #pragma unroll
            for (int k = 0; k < 32; k++) {
                float w = aW1[k], bb = ab1[k];
                if (w * trep + bb > 0.0f) {
                    float w2 = aW2[k * 32 + o];
                    a = fmaf(bb, w2, a);
                    b = fmaf(w, w2, b);
                }
            }
            g_aA[idx] = a;
            g_aB[idx] = b;
        }
    } else {
        float4 z = make_float4(0.f, 0.f, 0.f, 0.f);
        long nc = (long)g_nseg_a * (NMAX / 2);   // float4 count over g_cts
        long nb = (long)gridDim.x - SEGS - 1;
        long gid = (long)(blk - SEGS - 1) * blockDim.x + threadIdx.x;
        long stride = nb * blockDim.x;
        float4* c4 = (float4*)g_cts;
        for (long i = gid; i < nc; i += stride) c4[i] = z;
    }
}

// ---------------------------------------------------------------------------
// K3: front pass — packed edge bucketing (warp-aggregated) + angle scatter
// ---------------------------------------------------------------------------
__global__ void k_front(const int* __restrict__ ei, const float* __restrict__ ea,
                        const int* __restrict__ ai, const float* __restrict__ ang,
                        int E, int A) {
    __shared__ float sbe[32], sba[32];
    if (threadIdx.x < 32) { sbe[threadIdx.x] = g_bp_e[threadIdx.x]; sba[threadIdx.x] = g_bp_a[threadIdx.x]; }
    __syncthreads();
    int i = blockIdx.x * blockDim.x + threadIdx.x;
    int lane = threadIdx.x & 31;
    int nbe = g_nseg_e - 1;
    int nba = g_nseg_a - 1;

    bool valid = (i < E);
    float t = valid ? __ldg(ea + i) : 0.0f;
    int r = valid ? __ldg(ei + i) : 0;
    int c = valid ? __ldg(ei + E + i) : 0;
    int seg = 0;
    for (int k = 0; k < nbe; k++) seg += (sbe[k] <= t) ? 1 : 0;
    int ns = nbe + 1;
    for (int s = 0; s < ns; s++) {
        unsigned mask = __ballot_sync(FULL, valid && (seg == s));
        if (mask) {
            int leader = __ffs(mask) - 1;
            int base = 0;
            if (lane == leader) base = atomicAdd(&g_ecnt[s], __popc(mask));
            base = __shfl_sync(FULL, base, leader);
            if (valid && seg == s) {
                int pos = base + __popc(mask & ((1u << lane) - 1u));
                g_ebuckp[s * EMAX + pos] = make_int4(r, c, __float_as_int(t), 0);
            }
        }
    }

    if (i < A) {
        float ta = __ldg(ang + i);
        int j = __ldg(ai + A + i);
        int sa = 0;
        for (int k = 0; k < nba; k++) sa += (sba[k] <= ta) ? 1 : 0;
        float2* p = &g_cts[sa * NMAX + j];
        atomicAdd(&p->x, 1.0f);
        atomicAdd(&p->y, ta);
    }
}

// ---------------------------------------------------------------------------
// K3.5: angle expansion, coalesced two-phase. Block = 128 nodes.
//   Phase1: coalesced stage of (cnt,ts) for <=ACH segments into smem.
//   Phase2: warp-per-node, branchless FMA from smem broadcasts, plain store
//   (doubles as the `out` initializer). Must run before k_edge.
// ---------------------------------------------------------------------------
__global__ void k_angle(float* __restrict__ out, int N) {
    __shared__ float2 scts[ACH][128];
    int tid = threadIdx.x;           // 128
    int lane = tid & 31, w = tid >> 5;
    int j0 = blockIdx.x * 128;
    int na = g_nseg_a;

    for (int c0 = 0; c0 < na; c0 += ACH) {
        int ce = na - c0; if (ce > ACH) ce = ACH;
        if (c0) __syncthreads();     // protect smem reuse across passes
        int j = j0 + tid;
        for (int s = 0; s < ce; s++)
            scts[s][tid] = (j < N) ? g_cts[(c0 + s) * NMAX + j] : make_float2(0.f, 0.f);
        __syncthreads();

        // per-warp: 32 nodes, lane = channel
        float aAr[ACH], aBr[ACH];
        for (int s = 0; s < ce; s++) {
            aAr[s] = g_aA[(c0 + s) * 32 + lane];   // L1-resident
            aBr[s] = g_aB[(c0 + s) * 32 + lane];
        }
        #pragma unroll 4
        for (int jj = 0; jj < 32; jj++) {
            int jn = j0 + w * 32 + jj;
            if (jn >= N) break;
            float acc = (c0 == 0) ? 0.0f : out[jn * 32 + lane];
            for (int s = 0; s < ce; s++) {
                float2 ct = scts[s][w * 32 + jj];  // LDS broadcast
                acc = fmaf(ct.x, aAr[s], acc);
                acc = fmaf(ct.y, aBr[s], acc);
            }
            out[jn * 32 + lane] = acc;
        }
    }
}

// ---------------------------------------------------------------------------
// K4: edge branch. Warp per 4 edges/iter, branchless, 8 interleaved FFMA2
//     chains, results staged to smem then flushed with red.global.add.v4.f32.
// ---------------------------------------------------------------------------
__global__ void __launch_bounds__(128, 4)
k_edge(const float* __restrict__ x, float* __restrict__ out) {
    __shared__ __align__(16) float stage[4][128];
    __shared__ __align__(16) float stres[4][128];
    int lane = threadIdx.x & 31;
    int wi = threadIdx.x >> 5;
    int gw = blockIdx.x * 4 + wi;
    int q_my = lane >> 3;
    int sub = lane & 7;

    int ns = g_nseg_e;
    for (int s = 0; s < ns; s++) {
        int cnt = g_ecnt[s];
        int idx = gw * 4;
        if (idx >= cnt) continue;

        ull abA[16], abB[16];
        const ull* T = g_AB + s * 1024;
        #pragma unroll
        for (int k = 0; k < 16; k++) {
            abA[k] = T[k * 32 + lane];
            abB[k] = T[512 + k * 32 + lane];
        }

        const int4* __restrict__ buck = g_ebuckp + s * EMAX;

        int ep = idx + q_my; if (ep > cnt - 1) ep = cnt - 1;
        int4 pm = __ldg(buck + ep);
        float4 xf = __ldg((const float4*)(x + pm.y * 32) + sub);

        while (idx < cnt) {
            ((float4*)stage[wi])[lane] = xf;
            __syncwarp();
            int cur = idx;
            idx += NWARP * 4;
            if (idx < cnt) {
                int en = idx + q_my; if (en > cnt - 1) en = cnt - 1;
                pm = __ldg(buck + en);
                xf = __ldg((const float4*)(x + pm.y * 32) + sub);
            }

            int m = cnt - 1;
            int4 p0 = __ldg(buck + cur);
            int4 p1 = __ldg(buck + (cur + 1 > m ? m : cur + 1));
            int4 p2 = __ldg(buck + (cur + 2 > m ? m : cur + 2));
            int4 p3 = __ldg(buck + (cur + 3 > m ? m : cur + 3));

            const ulonglong2* __restrict__ sv = (const ulonglong2*)stage[wi];
            ull aA0 = 0, aB0 = 0, aA1 = 0, aB1 = 0, aA2 = 0, aB2 = 0, aA3 = 0, aB3 = 0;
            #pragma unroll
            for (int j = 0; j < 8; j++) {
                ulonglong2 v0 = sv[j], v1 = sv[8 + j], v2 = sv[16 + j], v3 = sv[24 + j];
                asm("fma.rn.f32x2 %0, %1, %2, %0;" : "+l"(aA0) : "l"(v0.x), "l"(abA[2 * j]));
                asm("fma.rn.f32x2 %0, %1, %2, %0;" : "+l"(aB0) : "l"(v0.x), "l"(abB[2 * j]));
                asm("fma.rn.f32x2 %0, %1, %2, %0;" : "+l"(aA1) : "l"(v1.x), "l"(abA[2 * j]));
                asm("fma.rn.f32x2 %0, %1, %2, %0;" : "+l"(aB1) : "l"(v1.x), "l"(abB[2 * j]));
                asm("fma.rn.f32x2 %0, %1, %2, %0;" : "+l"(aA2) : "l"(v2.x), "l"(abA[2 * j]));
                asm("fma.rn.f32x2 %0, %1, %2, %0;" : "+l"(aB2) : "l"(v2.x), "l"(abB[2 * j]));
                asm("fma.rn.f32x2 %0, %1, %2, %0;" : "+l"(aA3) : "l"(v3.x), "l"(abA[2 * j]));
                asm("fma.rn.f32x2 %0, %1, %2, %0;" : "+l"(aB3) : "l"(v3.x), "l"(abB[2 * j]));
                asm("fma.rn.f32x2 %0, %1, %2, %0;" : "+l"(aA0) : "l"(v0.y), "l"(abA[2 * j + 1]));
                asm("fma.rn.f32x2 %0, %1, %2, %0;" : "+l"(aB0) : "l"(v0.y), "l"(abB[2 * j + 1]));
                asm("fma.rn.f32x2 %0, %1, %2, %0;" : "+l"(aA1) : "l"(v1.y), "l"(abA[2 * j + 1]));
                asm("fma.rn.f32x2 %0, %1, %2, %0;" : "+l"(aB1) : "l"(v1.y), "l"(abB[2 * j + 1]));
                asm("fma.rn.f32x2 %0, %1, %2, %0;" : "+l"(aA2) : "l"(v2.y), "l"(abA[2 * j + 1]));
                asm("fma.rn.f32x2 %0, %1, %2, %0;" : "+l"(aB2) : "l"(v2.y), "l"(abB[2 * j + 1]));
                asm("fma.rn.f32x2 %0, %1, %2, %0;" : "+l"(aA3) : "l"(v3.y), "l"(abA[2 * j + 1]));
                asm("fma.rn.f32x2 %0, %1, %2, %0;" : "+l"(aB3) : "l"(v3.y), "l"(abB[2 * j + 1]));
            }
            float alo, ahi, blo, bhi;
            asm("mov.b64 {%0, %1}, %2;" : "=f"(alo), "=f"(ahi) : "l"(aA0));
            asm("mov.b64 {%0, %1}, %2;" : "=f"(blo), "=f"(bhi) : "l"(aB0));
            stres[wi][lane] = fmaf(__int_as_float(p0.z), blo + bhi, alo + ahi);
            asm("mov.b64 {%0, %1}, %2;" : "=f"(alo), "=f"(ahi) : "l"(aA1));
            asm("mov.b64 {%0, %1}, %2;" : "=f"(blo), "=f"(bhi) : "l"(aB1));
            stres[wi][32 + lane] = fmaf(__int_as_float(p1.z), blo + bhi, alo + ahi);
            asm("mov.b64 {%0, %1}, %2;" : "=f"(alo), "=f"(ahi) : "l"(aA2));
            asm("mov.b64 {%0, %1}, %2;" : "=f"(blo), "=f"(bhi) : "l"(aB2));
            stres[wi][64 + lane] = fmaf(__int_as_float(p2.z), blo + bhi, alo + ahi);
            asm("mov.b64 {%0, %1}, %2;" : "=f"(alo), "=f"(ahi) : "l"(aA3));
            asm("mov.b64 {%0, %1}, %2;" : "=f"(blo), "=f"(bhi) : "l"(aB3));
            stres[wi][96 + lane] = fmaf(__int_as_float(p3.z), blo + bhi, alo + ahi);
            __syncwarp();

            int row = (q_my == 0) ? p0.x : (q_my == 1) ? p1.x : (q_my == 2) ? p2.x : p3.x;
            if (cur + q_my < cnt) {
                float4 v = ((const float4*)stres[wi])[lane];
                float* dst = out + row * 32 + sub * 4;
                asm volatile("red.global.add.v4.f32 [%0], {%1, %2, %3, %4};"
                             :: "l"(dst), "f"(v.x), "f"(v.y), "f"(v.z), "f"(v.w)
                             : "memory");
            }
            __syncwarp();
        }
    }
}

// ---------------------------------------------------------------------------
extern "C" void kernel_launch(void* const* d_in, const int* in_sizes, int n_in,
                              void* d_out, int out_size) {
    const float* x   = (const float*)d_in[0];
    const int*   ei  = (const int*)d_in[1];
    const float* ea  = (const float*)d_in[2];
    const int*   ai  = (const int*)d_in[3];
    const float* ang = (const float*)d_in[4];
    const float* eW1 = (const float*)d_in[5];
    const float* eb1 = (const float*)d_in[6];
    const float* eW2 = (const float*)d_in[7];
    const float* eb2 = (const float*)d_in[8];
    const float* aW1 = (const float*)d_in[9];
    const float* ab1 = (const float*)d_in[10];
    const float* aW2 = (const float*)d_in[11];
    const float* ab2 = (const float*)d_in[12];
    float* out = (float*)d_out;

    int N = in_sizes[0] / CH;
    int E = in_sizes[1] / 2;
    int A = in_sizes[3] / 3;

    k_pre<<<1, 64>>>(eW1, eb1, aW1, ab1);
    k_setup<<<SEGS + 1 + 256, 256>>>(eW1, eb1, eW2, eb2, aW1, ab1, aW2, ab2);
    int fb = ((E > A ? E : A) + 255) / 256;
    k_front<<<fb, 256>>>(ei, ea, ai, ang, E, A);
    k_angle<<<(N + 127) / 128, 128>>>(out, N);
    k_edge<<<NBLK, 128>>>(x, out);
}

// round 9
// speedup vs baseline: 1.9188x; 1.0632x over previous
#include <cuda_runtime.h>

#define CH 32
#define SEGS 33
#define NMAX 50000
#define EMAX 200000
#define FULL 0xffffffffu
#define NBLK 592
#define NWARP (NBLK * 4)
#define ACH 8

typedef unsigned long long ull;

// ---- device-global scratch ----
__device__ float g_bp_e[32], g_bp_a[32];          // compacted breakpoints
__device__ int   g_nseg_e, g_nseg_a;              // effective segment counts
// per segment: [0,512) = PA pairs {A[2k][o],A[2k+1][o]}, [512,1024) = PB pairs
__device__ ull   g_AB[SEGS * 1024];
__device__ float g_aA[SEGS * 32], g_aB[SEGS * 32];
__device__ int   g_ecnt[SEGS];                    // per-segment edge count / cursor
__device__ __align__(16) int4 g_ebuckp[SEGS * EMAX]; // packed {row, col, t_bits, 0}
__device__ __align__(16) float2 g_cts[SEGS * NMAX];  // (count, sum_t) per (seg, node)

// ---------------------------------------------------------------------------
// warp-level breakpoint extraction + rank sort into `sorted`; returns count.
// ---------------------------------------------------------------------------
__device__ __forceinline__ int bp_sort(const float* __restrict__ W,
                                       const float* __restrict__ Bv,
                                       int lane, float* sorted) {
    float w = W[lane], b = Bv[lane];
    float p = (w != 0.0f) ? (-b / w) : -1.0f;
    bool valid = (p > 0.0f && p < 1.0f);
    unsigned vm = __ballot_sync(FULL, valid);
    int c = __popc(vm);
    int rank = 0;
    #pragma unroll
    for (int i = 0; i < 32; i++) {
        float pi = __shfl_sync(FULL, p, i);
        bool vi = (vm >> i) & 1u;
        if (vi && (pi < p || (pi == p && i < lane))) rank++;
    }
    if (valid) sorted[rank] = p;
    __syncwarp();
    return c;
}

// ---------------------------------------------------------------------------
// K1: table build (blocks 0..SEGS) + publish breakpoints (block SEGS) +
//     zero out/g_cts (remaining blocks). Breakpoints recomputed per block.
// ---------------------------------------------------------------------------
__global__ void k_setup(const float* __restrict__ eW1, const float* __restrict__ eb1,
                        const float* __restrict__ eW2, const float* __restrict__ eb2,
                        const float* __restrict__ aW1, const float* __restrict__ ab1,
                        const float* __restrict__ aW2, const float* __restrict__ ab2,
                        float* __restrict__ out, int N) {
    int blk = blockIdx.x;
    if (blk < SEGS) {
        // ---- edge table for segment s = blk ----
        __shared__ float sbp[33];
        __shared__ int scnt;
        __shared__ float w1[32], b1[32];
        if (threadIdx.x < 32) {
            int c = bp_sort(eW1, eb1, threadIdx.x, sbp);
            if (threadIdx.x == 0) scnt = c;
        }
        if (threadIdx.x >= 32 && threadIdx.x < 64) {
            int l = threadIdx.x - 32;
            w1[l] = eW1[l]; b1[l] = eb1[l];
        }
        __syncthreads();
        int c = scnt;
        int s = blk;
        if (s > c) return;                 // segment doesn't exist
        float lo = (s == 0) ? 0.0f : sbp[s - 1];
        float hi = (s == c) ? 1.0f : sbp[s];
        float trep = 0.5f * (lo + hi);
        float* ABf = (float*)g_AB;
        for (int io = threadIdx.x; io < 1024; io += blockDim.x) {
            float a = eb2[io], b = 0.0f;
            #pragma unroll
            for (int k = 0; k < 32; k++) {
                if (w1[k] * trep + b1[k] > 0.0f) {
                    float w2 = eW2[k * 1024 + io];
                    a = fmaf(b1[k], w2, a);
                    b = fmaf(w1[k], w2, b);
                }
            }
            int i = io >> 5, o = io & 31;
            int pa = s * 2048 + (i >> 1) * 64 + o * 2 + (i & 1);
            ABf[pa] = a;
            ABf[pa + 1024] = b;
        }
    } else if (blk == SEGS) {
        // ---- publish breakpoints + angle table + zero cursors ----
        __shared__ float se[33], sa[33];
        __shared__ int sce, sca;
        int warp = threadIdx.x >> 5, lane = threadIdx.x & 31;
        if (threadIdx.x < SEGS) g_ecnt[threadIdx.x] = 0;
        if (warp == 0) {
            int c = bp_sort(eW1, eb1, lane, se);
            g_bp_e[lane] = (lane < c) ? se[lane] : 2.0f;
            if (lane == 0) { g_nseg_e = c + 1; sce = c; }
        } else if (warp == 1) {
            int c = bp_sort(aW1, ab1, lane, sa);
            g_bp_a[lane] = (lane < c) ? sa[lane] : 2.0f;
            if (lane == 0) { g_nseg_a = c + 1; sca = c; }
        }
        __syncthreads();
        int ca = sca;
        int ns = ca + 1;
        for (int idx = threadIdx.x; idx < ns * 32; idx += blockDim.x) {
            int s2 = idx >> 5, o = idx & 31;
            float lo = (s2 == 0) ? 0.0f : sa[s2 - 1];
            float hi = (s2 == ca) ? 1.0f : sa[s2];
            float trep = 0.5f * (lo + hi);
            float a = ab2[o], b = 0.0f;
            #pragma unroll
            for (int k = 0; k < 32; k++) {
                float w = aW1[k], bb = ab1[k];
                if (w * trep + bb > 0.0f) {
                    float w2 = aW2[k * 32 + o];
                    a = fmaf(bb, w2, a);
                    b = fmaf(w, w2, b);
                }
            }
            g_aA[idx] = a;
            g_aB[idx] = b;
        }
    } else {
        // ---- zero out + g_cts ----
        __shared__ int sna;
        if (threadIdx.x < 32) {
            float w = aW1[threadIdx.x], b = ab1[threadIdx.x];
            float p = (w != 0.0f) ? (-b / w) : -1.0f;
            unsigned vm = __ballot_sync(FULL, p > 0.0f && p < 1.0f);
            if (threadIdx.x == 0) sna = __popc(vm) + 1;
        }
        __syncthreads();
        float4 z = make_float4(0.f, 0.f, 0.f, 0.f);
        long no = (long)N * 8;                 // float4 count for out
        long nc = (long)sna * (NMAX / 2);      // float4 count over g_cts
        long nb = (long)gridDim.x - SEGS - 1;
        long gid = (long)(blk - SEGS - 1) * blockDim.x + threadIdx.x;
        long stride = nb * blockDim.x;
        float4* o4 = (float4*)out;
        float4* c4 = (float4*)g_cts;
        for (long i = gid; i < no; i += stride) o4[i] = z;
        for (long i = gid; i < nc; i += stride) c4[i] = z;
    }
}

// ---------------------------------------------------------------------------
// K2: front pass — packed edge bucketing (warp-aggregated) + angle scatter
// ---------------------------------------------------------------------------
__global__ void k_front(const int* __restrict__ ei, const float* __restrict__ ea,
                        const int* __restrict__ ai, const float* __restrict__ ang,
                        int E, int A) {
    __shared__ float sbe[32], sba[32];
    if (threadIdx.x < 32) { sbe[threadIdx.x] = g_bp_e[threadIdx.x]; sba[threadIdx.x] = g_bp_a[threadIdx.x]; }
    __syncthreads();
    int i = blockIdx.x * blockDim.x + threadIdx.x;
    int lane = threadIdx.x & 31;
    int nbe = g_nseg_e - 1;
    int nba = g_nseg_a - 1;

    bool valid = (i < E);
    float t = valid ? __ldg(ea + i) : 0.0f;
    int r = valid ? __ldg(ei + i) : 0;
    int c = valid ? __ldg(ei + E + i) : 0;
    int seg = 0;
    for (int k = 0; k < nbe; k++) seg += (sbe[k] <= t) ? 1 : 0;
    int ns = nbe + 1;
    for (int s = 0; s < ns; s++) {
        unsigned mask = __ballot_sync(FULL, valid && (seg == s));
        if (mask) {
            int leader = __ffs(mask) - 1;
            int base = 0;
            if (lane == leader) base = atomicAdd(&g_ecnt[s], __popc(mask));
            base = __shfl_sync(FULL, base, leader);
            if (valid && seg == s) {
                int pos = base + __popc(mask & ((1u << lane) - 1u));
                g_ebuckp[s * EMAX + pos] = make_int4(r, c, __float_as_int(t), 0);
            }
        }
    }

    if (i < A) {
        float ta = __ldg(ang + i);
        int j = __ldg(ai + A + i);
        int sa = 0;
        for (int k = 0; k < nba; k++) sa += (sba[k] <= ta) ? 1 : 0;
        float2* p = &g_cts[sa * NMAX + j];
        atomicAdd(&p->x, 1.0f);
        atomicAdd(&p->y, ta);
    }
}

// ---------------------------------------------------------------------------
// K3: fused angle-expansion + edge kernel.
//   Phase A (per block, nodes [blockIdx.x*128, +128)): coalesced g_cts stage,
//   warp computes 4 nodes at a time, flush via red.global.add.v4.f32.
//   Phase B: R8 edge branch unchanged (register tables + FFMA2 + red.v4).
// ---------------------------------------------------------------------------
__global__ void __launch_bounds__(128, 4)
k_edge(const float* __restrict__ x, float* __restrict__ out, int N) {
    __shared__ __align__(16) float stage[4][128];
    __shared__ __align__(16) float stres[4][128];
    __shared__ float2 scts[ACH][128];
    int tid = threadIdx.x;
    int lane = tid & 31;
    int wi = tid >> 5;
    int gw = blockIdx.x * 4 + wi;
    int q_my = lane >> 3;
    int sub = lane & 7;

    // ================= Phase A: angle expansion =================
    int na = g_nseg_a;
    int j0 = blockIdx.x * 128;
    if (j0 < N) {
        int ce = na < ACH ? na : ACH;
        int jt = j0 + tid;
        for (int s = 0; s < ce; s++)
            scts[s][tid] = (jt < N) ? g_cts[s * NMAX + jt] : make_float2(0.f, 0.f);
        __syncthreads();

        float aAr[ACH], aBr[ACH];
        for (int s = 0; s < ce; s++) {
            aAr[s] = g_aA[s * 32 + lane];
            aBr[s] = g_aB[s * 32 + lane];
        }
        for (int g = 0; g < 8; g++) {
            int nb0 = wi * 32 + g * 4;           // node offset within block
            #pragma unroll
            for (int q = 0; q < 4; q++) {
                float acc = 0.0f;
                for (int s = 0; s < ce; s++) {
                    float2 ct = scts[s][nb0 + q];   // LDS broadcast
                    acc = fmaf(ct.x, aAr[s], acc);
                    acc = fmaf(ct.y, aBr[s], acc);
                }
                for (int s = ACH; s < na; s++) {    // rare overflow segments
                    int jn = j0 + nb0 + q;
                    float2 ct = (jn < N) ? g_cts[s * NMAX + jn] : make_float2(0.f, 0.f);
                    acc = fmaf(ct.x, g_aA[s * 32 + lane], acc);
                    acc = fmaf(ct.y, g_aB[s * 32 + lane], acc);
                }
                stres[wi][q * 32 + lane] = acc;
            }
            __syncwarp();
            int node = j0 + nb0 + q_my;
            if (node < N) {
                float4 v = ((const float4*)stres[wi])[lane];
                float* dst = out + node * 32 + sub * 4;
                asm volatile("red.global.add.v4.f32 [%0], {%1, %2, %3, %4};"
                             :: "l"(dst), "f"(v.x), "f"(v.y), "f"(v.z), "f"(v.w)
                             : "memory");
            }
            __syncwarp();
        }
    }

    // ================= Phase B: edge branch (R8) =================
    int ns = g_nseg_e;
    for (int s = 0; s < ns; s++) {
        int cnt = g_ecnt[s];
        int idx = gw * 4;
        if (idx >= cnt) continue;

        ull abA[16], abB[16];
        const ull* T = g_AB + s * 1024;
        #pragma unroll
        for (int k = 0; k < 16; k++) {
            abA[k] = T[k * 32 + lane];
            abB[k] = T[512 + k * 32 + lane];
        }

        const int4* __restrict__ buck = g_ebuckp + s * EMAX;

        int ep = idx + q_my; if (ep > cnt - 1) ep = cnt - 1;
        int4 pm = __ldg(buck + ep);
        float4 xf = __ldg((const float4*)(x + pm.y * 32) + sub);

        while (idx < cnt) {
            ((float4*)stage[wi])[lane] = xf;
            __syncwarp();
            int cur = idx;
            idx += NWARP * 4;
            if (idx < cnt) {
                int en = idx + q_my; if (en > cnt - 1) en = cnt - 1;
                pm = __ldg(buck + en);
                xf = __ldg((const float4*)(x + pm.y * 32) + sub);
            }

            int m = cnt - 1;
            int4 p0 = __ldg(buck + cur);
            int4 p1 = __ldg(buck + (cur + 1 > m ? m : cur + 1));
            int4 p2 = __ldg(buck + (cur + 2 > m ? m : cur + 2));
            int4 p3 = __ldg(buck + (cur + 3 > m ? m : cur + 3));

            const ulonglong2* __restrict__ sv = (const ulonglong2*)stage[wi];
            ull aA0 = 0, aB0 = 0, aA1 = 0, aB1 = 0, aA2 = 0, aB2 = 0, aA3 = 0, aB3 = 0;
            #pragma unroll
            for (int j = 0; j < 8; j++) {
                ulonglong2 v0 = sv[j], v1 = sv[8 + j], v2 = sv[16 + j], v3 = sv[24 + j];
                asm("fma.rn.f32x2 %0, %1, %2, %0;" : "+l"(aA0) : "l"(v0.x), "l"(abA[2 * j]));
                asm("fma.rn.f32x2 %0, %1, %2, %0;" : "+l"(aB0) : "l"(v0.x), "l"(abB[2 * j]));
                asm("fma.rn.f32x2 %0, %1, %2, %0;" : "+l"(aA1) : "l"(v1.x), "l"(abA[2 * j]));
                asm("fma.rn.f32x2 %0, %1, %2, %0;" : "+l"(aB1) : "l"(v1.x), "l"(abB[2 * j]));
                asm("fma.rn.f32x2 %0, %1, %2, %0;" : "+l"(aA2) : "l"(v2.x), "l"(abA[2 * j]));
                asm("fma.rn.f32x2 %0, %1, %2, %0;" : "+l"(aB2) : "l"(v2.x), "l"(abB[2 * j]));
                asm("fma.rn.f32x2 %0, %1, %2, %0;" : "+l"(aA3) : "l"(v3.x), "l"(abA[2 * j]));
                asm("fma.rn.f32x2 %0, %1, %2, %0;" : "+l"(aB3) : "l"(v3.x), "l"(abB[2 * j]));
                asm("fma.rn.f32x2 %0, %1, %2, %0;" : "+l"(aA0) : "l"(v0.y), "l"(abA[2 * j + 1]));
                asm("fma.rn.f32x2 %0, %1, %2, %0;" : "+l"(aB0) : "l"(v0.y), "l"(abB[2 * j + 1]));
                asm("fma.rn.f32x2 %0, %1, %2, %0;" : "+l"(aA1) : "l"(v1.y), "l"(abA[2 * j + 1]));
                asm("fma.rn.f32x2 %0, %1, %2, %0;" : "+l"(aB1) : "l"(v1.y), "l"(abB[2 * j + 1]));
                asm("fma.rn.f32x2 %0, %1, %2, %0;" : "+l"(aA2) : "l"(v2.y), "l"(abA[2 * j + 1]));
                asm("fma.rn.f32x2 %0, %1, %2, %0;" : "+l"(aB2) : "l"(v2.y), "l"(abB[2 * j + 1]));
                asm("fma.rn.f32x2 %0, %1, %2, %0;" : "+l"(aA3) : "l"(v3.y), "l"(abA[2 * j + 1]));
                asm("fma.rn.f32x2 %0, %1, %2, %0;" : "+l"(aB3) : "l"(v3.y), "l"(abB[2 * j + 1]));
            }
            float alo, ahi, blo, bhi;
            asm("mov.b64 {%0, %1}, %2;" : "=f"(alo), "=f"(ahi) : "l"(aA0));
            asm("mov.b64 {%0, %1}, %2;" : "=f"(blo), "=f"(bhi) : "l"(aB0));
            stres[wi][lane] = fmaf(__int_as_float(p0.z), blo + bhi, alo + ahi);
            asm("mov.b64 {%0, %1}, %2;" : "=f"(alo), "=f"(ahi) : "l"(aA1));
            asm("mov.b64 {%0, %1}, %2;" : "=f"(blo), "=f"(bhi) : "l"(aB1));
            stres[wi][32 + lane] = fmaf(__int_as_float(p1.z), blo + bhi, alo + ahi);
            asm("mov.b64 {%0, %1}, %2;" : "=f"(alo), "=f"(ahi) : "l"(aA2));
            asm("mov.b64 {%0, %1}, %2;" : "=f"(blo), "=f"(bhi) : "l"(aB2));
            stres[wi][64 + lane] = fmaf(__int_as_float(p2.z), blo + bhi, alo + ahi);
            asm("mov.b64 {%0, %1}, %2;" : "=f"(alo), "=f"(ahi) : "l"(aA3));
            asm("mov.b64 {%0, %1}, %2;" : "=f"(blo), "=f"(bhi) : "l"(aB3));
            stres[wi][96 + lane] = fmaf(__int_as_float(p3.z), blo + bhi, alo + ahi);
            __syncwarp();

            int row = (q_my == 0) ? p0.x : (q_my == 1) ? p1.x : (q_my == 2) ? p2.x : p3.x;
            if (cur + q_my < cnt) {
                float4 v = ((const float4*)stres[wi])[lane];
                float* dst = out + row * 32 + sub * 4;
                asm volatile("red.global.add.v4.f32 [%0], {%1, %2, %3, %4};"
                             :: "l"(dst), "f"(v.x), "f"(v.y), "f"(v.z), "f"(v.w)
                             : "memory");
            }
            __syncwarp();
        }
    }
}

// ---------------------------------------------------------------------------
extern "C" void kernel_launch(void* const* d_in, const int* in_sizes, int n_in,
                              void* d_out, int out_size) {
    const float* x   = (const float*)d_in[0];
    const int*   ei  = (const int*)d_in[1];
    const float* ea  = (const float*)d_in[2];
    const int*   ai  = (const int*)d_in[3];
    const float* ang = (const float*)d_in[4];
    const float* eW1 = (const float*)d_in[5];
    const float* eb1 = (const float*)d_in[6];
    const float* eW2 = (const float*)d_in[7];
    const float* eb2 = (const float*)d_in[8];
    const float* aW1 = (const float*)d_in[9];
    const float* ab1 = (const float*)d_in[10];
    const float* aW2 = (const float*)d_in[11];
    const float* ab2 = (const float*)d_in[12];
    float* out = (float*)d_out;

    int N = in_sizes[0] / CH;
    int E = in_sizes[1] / 2;
    int A = in_sizes[3] / 3;

    k_setup<<<SEGS + 1 + 256, 256>>>(eW1, eb1, eW2, eb2, aW1, ab1, aW2, ab2, out, N);
    int fb = ((E > A ? E : A) + 255) / 256;
    k_front<<<fb, 256>>>(ei, ea, ai, ang, E, A);
    k_edge<<<NBLK, 128>>>(x, out, N);
}